// round 12
// baseline (speedup 1.0000x reference)
#include <cuda_runtime.h>

// ---------------------------------------------------------------------------
// N=262144 rows, three streams x[N,80]. R_a = BN(x W_a^T + b_a) (batch stats).
// sims = rowwise dots of R pairs -> softmax over 3 -> blend of inputs.
//
// Closed forms:
//   mu_j  = w_j.xbar + b_j
//   var_j = w_j^T (X^T X / N) w_j - (w_j.xbar)^2
//   sim_ab(i) = x_a^T M_ab x_b + u_ab.x_a + v_ab.x_b + c_ab,  M_ab = Wh_a^T Wh_b
//
// R11: zero-MOV ffma2 inner loops. k_xtx lanes = row pairs (transposed tile);
// k_main XT stored q-pair-packed so both ffma2 operands load pre-packed.
// ---------------------------------------------------------------------------

#define DIN    80
#define DOUT   160
#define NROWS  262144
#define EPSV   1e-5f

#define P1_BLOCKS  256        // blocks per stream (pass 1)
#define P1_TILES   8          // 128-row tiles per block: 256*8*128 = 262144
#define P1_THREADS 256
#define P1P 130               // transposed tile pitch (floats)

#define BR 64                 // rows per block (pass 2)
#define P2 66                 // XT2 pitch in float2 units (64 + 2 pad)

// ---- device scratch (static: no runtime allocation allowed) ---------------
__device__ float gSpart[3 * P1_BLOCKS * DIN];            // per-block col sums
__device__ float gS[3 * DIN];                            // column sums
__device__ float gCpart[(size_t)3 * P1_BLOCKS * DIN*DIN];// per-block XtX partials
__device__ float gC[3 * DIN * DIN];                      // XtX per stream
__device__ float gM[3 * DIN * DIN];                      // bilinear matrices
__device__ float gU[3 * DIN];
__device__ float gV[3 * DIN];
__device__ float gCc[3];

struct Params {
    const float* W[3];
    const float* b[3];
    const float* g[3];
    const float* be[3];
};

// packed dual FMA (fma-pipe 2x vs scalar FFMA; PTX-only on sm_10x)
__device__ __forceinline__ float2 ffma2(float2 a, float2 b, float2 c) {
    float2 d;
    asm("fma.rn.f32x2 %0, %1, %2, %3;"
        : "=l"(reinterpret_cast<unsigned long long&>(d))
        : "l"(reinterpret_cast<unsigned long long&>(a)),
          "l"(reinterpret_cast<unsigned long long&>(b)),
          "l"(reinterpret_cast<unsigned long long&>(c)));
    return d;
}

// ---------------------------------------------------------------------------
// K1: per-block partial X^T X (upper block-triangle) + column-sum partials.
// 256 threads = 16(tj) x 16(tk); 5x5 scalar tile, float2 acc lanes = ROW
// PAIRS from the transposed tile XsT[q][r] -> both ffma2 operands are natural
// LDS.64, zero packing MOVs. Lane-sum once at the store.
// ---------------------------------------------------------------------------
__global__ __launch_bounds__(P1_THREADS)
void k_xtx(const float* __restrict__ X0, const float* __restrict__ X1,
           const float* __restrict__ X2)
{
    __shared__ __align__(16) float XsT[DIN * P1P];   // [q][r], 41.6 KB

    const int s = blockIdx.y;
    const float* X = (s == 0) ? X0 : (s == 1) ? X1 : X2;
    const int tid = threadIdx.x;
    const int tj = tid & 15;      // j = tj + 16a
    const int tk = tid >> 4;      // k = tk + 16b

    float2 acc[5][5];
#pragma unroll
    for (int a = 0; a < 5; ++a)
#pragma unroll
        for (int b = 0; b < 5; ++b) acc[a][b] = make_float2(0.f, 0.f);
    float2 cs = make_float2(0.f, 0.f);
    const float2 one2 = make_float2(1.f, 1.f);

    const long long rowbase = (long long)blockIdx.x * (P1_TILES * 128);

    for (int t = 0; t < P1_TILES; ++t) {
        // transpose 128x80 tile into XsT[q][r] (coalesced LDG.128)
        const float4* src4 =
            (const float4*)(X + (rowbase + (long long)t * 128) * DIN);
        for (int i4 = tid; i4 < 128 * DIN / 4; i4 += P1_THREADS) {
            int r  = i4 / 20;
            int k4 = i4 - r * 20;
            float4 v = src4[i4];
            XsT[(4 * k4 + 0) * P1P + r] = v.x;
            XsT[(4 * k4 + 1) * P1P + r] = v.y;
            XsT[(4 * k4 + 2) * P1P + r] = v.z;
            XsT[(4 * k4 + 3) * P1P + r] = v.w;
        }
        __syncthreads();

#pragma unroll 4
        for (int p = 0; p < 64; ++p) {        // 64 row pairs
            float2 xj[5], xk[5];
#pragma unroll
            for (int a = 0; a < 5; ++a)
                xj[a] = *(const float2*)&XsT[(tj + 16 * a) * P1P + 2 * p];
#pragma unroll
            for (int b = 0; b < 5; ++b)
                xk[b] = *(const float2*)&XsT[(tk + 16 * b) * P1P + 2 * p];
#pragma unroll
            for (int a = 0; a < 5; ++a)
#pragma unroll
                for (int b = a; b < 5; ++b)
                    acc[a][b] = ffma2(xj[a], xk[b], acc[a][b]);
        }

        if (tid < DIN) {                      // column sums (contiguous row)
#pragma unroll 8
            for (int p = 0; p < 64; ++p)
                cs = ffma2(*(const float2*)&XsT[tid * P1P + 2 * p], one2, cs);
        }
        __syncthreads();
    }

    float* dst = gCpart + (size_t)(s * P1_BLOCKS + blockIdx.x) * (DIN * DIN);
#pragma unroll
    for (int a = 0; a < 5; ++a)
#pragma unroll
        for (int b = a; b < 5; ++b)
            dst[(tj + 16 * a) * DIN + (tk + 16 * b)] = acc[a][b].x + acc[a][b].y;
    if (tid < DIN)
        gSpart[(s * P1_BLOCKS + blockIdx.x) * DIN + tid] = cs.x + cs.y;
}

// ---------------------------------------------------------------------------
// K2: reduce partials -> gC (mirror lower triangle) and gSpart -> gS.
// ---------------------------------------------------------------------------
__global__ void k_reduceC()
{
    int e = blockIdx.x * blockDim.x + threadIdx.x;
    if (e < 3 * DIN * DIN) {
        int s   = e / (DIN * DIN);
        int rem = e - s * DIN * DIN;
        int j = rem / DIN, k = rem - j * DIN;
        int jt = j >> 4, kt = k >> 4;
        if (jt > kt || (jt == kt && j > k)) return;   // mirror handles these

        const float* src = gCpart + (size_t)s * P1_BLOCKS * (DIN * DIN) + rem;
        float acc = 0.f;
#pragma unroll 8
        for (int b = 0; b < P1_BLOCKS; ++b)
            acc += src[(size_t)b * (DIN * DIN)];
        gC[s * DIN * DIN + j * DIN + k] = acc;
        gC[s * DIN * DIN + k * DIN + j] = acc;
    } else if (e < 3 * DIN * DIN + 3 * DIN) {
        int h = e - 3 * DIN * DIN;
        int s = h / DIN, k = h - s * DIN;
        float acc = 0.f;
#pragma unroll 8
        for (int b = 0; b < P1_BLOCKS; ++b)
            acc += gSpart[(s * P1_BLOCKS + b) * DIN + k];
        gS[s * DIN + k] = acc;
    }
}

// ---------------------------------------------------------------------------
// K3 (fused stats + buildM): grid = 3 blocks (one per pair), 256 threads.
// ---------------------------------------------------------------------------
#define WP 84                                   // W smem pitch
#define TPP (DOUT + 8)                          // Tpart pitch
#define PREP_FLOATS (2*DOUT*WP + DIN*DIN + 16*TPP + DOUT + DIN + 2*DOUT)
#define PREP_SMEM (PREP_FLOATS * 4)

__global__ __launch_bounds__(256)
void k_prep(Params P, float invN)
{
    extern __shared__ __align__(16) float sp[];
    float* WsA    = sp;                         // [160][WP]
    float* WsB    = WsA + DOUT * WP;            // [160][WP]
    float* Cs     = WsB + DOUT * WP;            // [80][80]
    float* Tp     = Cs + DIN * DIN;             // [16][TPP]
    float* alphas = Tp + 16 * TPP;              // [160]
    float* xbs    = alphas + DOUT;              // [80]
    float* dA     = xbs + DIN;                  // [160]
    float* dB     = dA + DOUT;                  // [160]

    const int s = blockIdx.x;
    const int a_idx = (s == 2) ? 1 : 0;         // pa = {0,0,1}
    const int b_idx = (s == 0) ? 1 : 2;         // pb = {1,2,2}
    const int tid = threadIdx.x;
    const int tj = tid & 15, tk = tid >> 4;

    for (int ph = 0; ph < 2; ++ph) {
        const int t  = ph ? b_idx : a_idx;
        float* Ws    = ph ? WsB : WsA;
        float* dd    = ph ? dB : dA;

        const float4* Wg4 = (const float4*)P.W[t];
        for (int i4 = tid; i4 < DOUT * 20; i4 += 256) {
            int j = i4 / 20, k4 = i4 - j * 20;
            *(float4*)&Ws[j * WP + 4 * k4] = Wg4[i4];
        }
        const float4* Cg4 = (const float4*)&gC[t * DIN * DIN];
        float4* Cs4 = (float4*)Cs;
        for (int i4 = tid; i4 < (DIN * DIN) / 4; i4 += 256) Cs4[i4] = Cg4[i4];
        if (tid < DIN) xbs[tid] = gS[t * DIN + tid] * invN;
        __syncthreads();

        float acc[10][5];
#pragma unroll
        for (int aa = 0; aa < 10; ++aa)
#pragma unroll
            for (int bb = 0; bb < 5; ++bb) acc[aa][bb] = 0.f;

        for (int m = 0; m < DIN; ++m) {
            float wv[10], cv[5];
#pragma unroll
            for (int aa = 0; aa < 10; ++aa) wv[aa] = Ws[(tj + 16 * aa) * WP + m];
#pragma unroll
            for (int bb = 0; bb < 5; ++bb)  cv[bb] = Cs[m * DIN + tk + 16 * bb];
#pragma unroll
            for (int aa = 0; aa < 10; ++aa)
#pragma unroll
                for (int bb = 0; bb < 5; ++bb)
                    acc[aa][bb] += wv[aa] * cv[bb];
        }
#pragma unroll
        for (int aa = 0; aa < 10; ++aa) {
            float psum = 0.f;
#pragma unroll
            for (int bb = 0; bb < 5; ++bb)
                psum += acc[aa][bb] * Ws[(tj + 16 * aa) * WP + tk + 16 * bb];
            Tp[tk * TPP + tj + 16 * aa] = psum;
        }
        __syncthreads();

        if (tid < DOUT) {
            float q = 0.f;
#pragma unroll
            for (int g = 0; g < 16; ++g) q += Tp[g * TPP + tid];
            float wx = 0.f;
#pragma unroll 8
            for (int m = 0; m < DIN; ++m) wx += Ws[tid * WP + m] * xbs[m];
            float bj    = P.b[t][tid];
            float mu    = wx + bj;
            float var   = q * invN - wx * wx;
            float alpha = P.g[t][tid] * rsqrtf(var + EPSV);
            dd[tid]     = alpha * bj + (P.be[t][tid] - mu * alpha);
            alphas[tid] = alpha;
        }
        __syncthreads();

        for (int i = tid; i < DOUT * DIN; i += 256) {
            int j = i / DIN, m = i - j * DIN;
            Ws[j * WP + m] *= alphas[j];
        }
        __syncthreads();
    }

    float macc[5][5];
#pragma unroll
    for (int aa = 0; aa < 5; ++aa)
#pragma unroll
        for (int bb = 0; bb < 5; ++bb) macc[aa][bb] = 0.f;

    for (int j = 0; j < DOUT; ++j) {
        float av[5], bv[5];
#pragma unroll
        for (int aa = 0; aa < 5; ++aa) av[aa] = WsA[j * WP + tj + 16 * aa];
#pragma unroll
        for (int bb = 0; bb < 5; ++bb) bv[bb] = WsB[j * WP + tk + 16 * bb];
#pragma unroll
        for (int aa = 0; aa < 5; ++aa)
#pragma unroll
            for (int bb = 0; bb < 5; ++bb)
                macc[aa][bb] += av[aa] * bv[bb];
    }
#pragma unroll
    for (int aa = 0; aa < 5; ++aa)
#pragma unroll
        for (int bb = 0; bb < 5; ++bb)
            gM[s * DIN * DIN + (tj + 16 * aa) * DIN + (tk + 16 * bb)] =
                macc[aa][bb];

    if (tid < DIN) {
        float u = 0.f;
        for (int j = 0; j < DOUT; ++j) u += WsA[j * WP + tid] * dB[j];
        gU[s * DIN + tid] = u;
    } else if (tid < 2 * DIN) {
        int q = tid - DIN;
        float v = 0.f;
        for (int j = 0; j < DOUT; ++j) v += dA[j] * WsB[j * WP + q];
        gV[s * DIN + q] = v;
    } else if (tid == 2 * DIN) {
        float c = 0.f;
        for (int j = 0; j < DOUT; ++j) c += dA[j] * dB[j];
        gCc[s] = c;
    }
}

// ---------------------------------------------------------------------------
// K4: main pass. 64 rows/block, 256 threads = 16(tr: 4 rows) x 16(tc: 5 p).
// XT stored q-pair-packed (float2 lanes = q, q+1): xv = 2x LDS.128 pre-packed,
// mv = natural LDS.64 from row-major M -> zero packing MOVs in the hot loop.
// u folded into the per-row dot phase. psum staging, no atomics.
// ---------------------------------------------------------------------------
#define SM_XT2  0                               // float2 [3][40][P2]
#define SM_M    (3 * 40 * P2 * 2)               // 15840
#define SM_U2   (SM_M + DIN * DIN)              // 22240  (float [3][80])
#define SM_V2   (SM_U2 + 3 * DIN)               // 22480
#define SM_SIM  (SM_V2 + 3 * DIN)               // 22720
#define SM_P    (SM_SIM + 3 * BR)               // 22912
#define SM_CC   (SM_P + 3 * BR)                 // 23104
#define SM_PS   (SM_CC + 8)                     // 23112
#define SM_TOT  (SM_PS + 16 * P2)               // 24168 floats
#define SMEM_BYTES (SM_TOT * 4)                 // 96672 B -> 2 blocks/SM

__global__ __launch_bounds__(256, 2)
void k_main(const float* __restrict__ X0, const float* __restrict__ X1,
            const float* __restrict__ X2, float* __restrict__ out)
{
    extern __shared__ __align__(16) float sm[];
    float2* XT2 = (float2*)(sm + SM_XT2); // [s][qq][r] lanes = (2qq, 2qq+1)
    float* Msm  = sm + SM_M;              // [80][80]
    float* usm  = sm + SM_U2;             // [3][80] (float2-viewable)
    float* vsm  = sm + SM_V2;             // [3][80]
    float* sims = sm + SM_SIM;            // [3][64]
    float* psm  = sm + SM_P;              // [3][64]
    float* ccs  = sm + SM_CC;             // [3]
    float* psum = sm + SM_PS;             // [16][P2]

    const int tid = threadIdx.x;
    const int tr  = tid & 15;     // rows 4*tr .. 4*tr+3
    const int tc  = tid >> 4;     // p = tc + 16*c
    const long long base = (long long)blockIdx.x * BR;

    // ---- phase A: load (float4) + pair-pack x tiles; load u, v, c ---------
    const float* Xp[3] = {X0, X1, X2};
    for (int s = 0; s < 3; ++s) {
        const float4* src4 = (const float4*)(Xp[s] + base * DIN);
        float2* dst = XT2 + s * 40 * P2;
        for (int i4 = tid; i4 < BR * DIN / 4; i4 += 256) {
            int r  = i4 / 20;
            int k4 = i4 - r * 20;
            float4 v = src4[i4];
            dst[(2 * k4 + 0) * P2 + r] = make_float2(v.x, v.y);
            dst[(2 * k4 + 1) * P2 + r] = make_float2(v.z, v.w);
        }
    }
    if (tid < 3 * DIN) { usm[tid] = gU[tid]; vsm[tid] = gV[tid]; }
    if (tid < 3)       ccs[tid] = gCc[tid];
    __syncthreads();

    for (int s = 0; s < 3; ++s) {
        // pa = {0,0,1}, pb = {1,2,2}
        const int a_idx = (s == 2) ? 1 : 0;
        const int b_idx = (s == 0) ? 1 : 2;

        const float4* Mg4 = (const float4*)&gM[s * DIN * DIN];
        float4* Ms4 = (float4*)Msm;
        for (int i = tid; i < (DIN * DIN) / 4; i += 256) Ms4[i] = Mg4[i];
        __syncthreads();

        const float2* Xb = XT2 + b_idx * 40 * P2;

        float2 acc[4][5];
#pragma unroll
        for (int r = 0; r < 4; ++r)
#pragma unroll
            for (int c = 0; c < 5; ++c) acc[r][c] = make_float2(0.f, 0.f);

#pragma unroll 4
        for (int qq = 0; qq < 40; ++qq) {
            float2 xv[4];
            *(float4*)&xv[0] = *(const float4*)&Xb[qq * P2 + 4 * tr];
            *(float4*)&xv[2] = *(const float4*)&Xb[qq * P2 + 4 * tr + 2];
            float2 mv[5];
#pragma unroll
            for (int c = 0; c < 5; ++c)
                mv[c] = *(const float2*)&Msm[(tc + 16 * c) * DIN + 2 * qq];
#pragma unroll
            for (int r = 0; r < 4; ++r)
#pragma unroll
                for (int c = 0; c < 5; ++c)
                    acc[r][c] = ffma2(xv[r], mv[c], acc[r][c]);
        }

        // ---- epilogue: part[r] = sum_c z[p] * x_a[p][4tr+r]  (u moved out)
        const float* XaF = (const float*)(XT2 + a_idx * 40 * P2);
        float part[4] = {0.f, 0.f, 0.f, 0.f};
#pragma unroll
        for (int c = 0; c < 5; ++c) {
            int p = tc + 16 * c;
            const float* ap = XaF + (p >> 1) * (2 * P2) + (p & 1);
#pragma unroll
            for (int r = 0; r < 4; ++r) {
                float z = acc[r][c].x + acc[r][c].y;
                part[r] += z * ap[2 * (4 * tr + r)];
            }
        }
#pragma unroll
        for (int r = 0; r < 4; ++r)
            psum[tc * P2 + 4 * tr + r] = part[r];
        __syncthreads();

        if (tid < BR) {                 // gather across the 16 tc groups
            float v = 0.f;
#pragma unroll
            for (int t = 0; t < 16; ++t) v += psum[t * P2 + tid];
            sims[s * BR + tid] = v;
        }
        __syncthreads();
    }

    // ---- per-row: u,v dots (lane-packed), + c, softmax over 3 sims --------
    if (tid < BR) {
        const int r = tid;
        const float2* x0 = XT2;
        const float2* x1 = XT2 + 40 * P2;
        const float2* x2 = XT2 + 80 * P2;
        const float2* u2 = (const float2*)usm;   // [3][40]
        const float2* v2 = (const float2*)vsm;
        float2 d0 = make_float2(0.f, 0.f), d1 = d0, d2 = d0;
#pragma unroll 8
        for (int qq = 0; qq < 40; ++qq) {
            float2 a  = x0[qq * P2 + r];
            float2 bb = x1[qq * P2 + r];
            float2 cc = x2[qq * P2 + r];
            d0 = ffma2(u2[qq],      a,  d0);
            d0 = ffma2(v2[qq],      bb, d0);
            d1 = ffma2(u2[40 + qq], a,  d1);
            d1 = ffma2(v2[40 + qq], cc, d1);
            d2 = ffma2(u2[80 + qq], bb, d2);
            d2 = ffma2(v2[80 + qq], cc, d2);
        }
        float s0 = sims[0 * BR + r] + d0.x + d0.y + ccs[0];
        float s1 = sims[1 * BR + r] + d1.x + d1.y + ccs[1];
        float s2 = sims[2 * BR + r] + d2.x + d2.y + ccs[2];
        float m  = fmaxf(s0, fmaxf(s1, s2));
        float e0 = __expf(s0 - m), e1 = __expf(s1 - m), e2 = __expf(s2 - m);
        float inv = 1.f / (e0 + e1 + e2);
        psm[0 * BR + r] = e0 * inv;
        psm[1 * BR + r] = e1 * inv;
        psm[2 * BR + r] = e2 * inv;
    }
    __syncthreads();

    // ---- blend + float4 store: out = p0*left + p1*right + p2*sub ----------
    float4* dst4 = (float4*)(out + base * DIN);
    for (int i4 = tid; i4 < BR * DIN / 4; i4 += 256) {
        int r  = i4 / 20;
        int k4 = i4 - r * 20;
        float p0 = psm[r], p1 = psm[BR + r], p2 = psm[2 * BR + r];
        float2 S0 = XT2[(2 * k4) * P2 + r],      S1 = XT2[(2 * k4 + 1) * P2 + r];
        float2 L0 = XT2[(40 + 2 * k4) * P2 + r], L1 = XT2[(40 + 2 * k4 + 1) * P2 + r];
        float2 R0 = XT2[(80 + 2 * k4) * P2 + r], R1 = XT2[(80 + 2 * k4 + 1) * P2 + r];
        float4 o;
        o.x = p0 * L0.x + p1 * R0.x + p2 * S0.x;
        o.y = p0 * L0.y + p1 * R0.y + p2 * S0.y;
        o.z = p0 * L1.x + p1 * R1.x + p2 * S1.x;
        o.w = p0 * L1.y + p1 * R1.y + p2 * S1.y;
        dst4[i4] = o;
    }
}

// ---------------------------------------------------------------------------
extern "C" void kernel_launch(void* const* d_in, const int* in_sizes, int n_in,
                              void* d_out, int out_size)
{
    const float* sub   = (const float*)d_in[0];
    const float* left  = (const float*)d_in[1];
    const float* right = (const float*)d_in[2];

    Params P;
    for (int s = 0; s < 3; ++s) {
        P.W[s]  = (const float*)d_in[3 + 4 * s + 0];
        P.b[s]  = (const float*)d_in[3 + 4 * s + 1];
        P.g[s]  = (const float*)d_in[3 + 4 * s + 2];
        P.be[s] = (const float*)d_in[3 + 4 * s + 3];
    }

    cudaFuncSetAttribute(k_prep, cudaFuncAttributeMaxDynamicSharedMemorySize,
                         PREP_SMEM);
    cudaFuncSetAttribute(k_main, cudaFuncAttributeMaxDynamicSharedMemorySize,
                         SMEM_BYTES);

    k_xtx<<<dim3(P1_BLOCKS, 3), P1_THREADS>>>(sub, left, right);
    k_reduceC<<<(3 * DIN * DIN + 3 * DIN + 255) / 256, 256>>>();
    k_prep<<<3, 256, PREP_SMEM>>>(P, 1.0f / (float)NROWS);
    k_main<<<NROWS / BR, 256, SMEM_BYTES>>>(sub, left, right, (float*)d_out);
}

// round 14
// speedup vs baseline: 1.2520x; 1.2520x over previous
#include <cuda_runtime.h>
#include <cuda_bf16.h>
#include <cstdint>

#define DIN 80
#define DOUT 160
#define NROWS 262144
#define EPSV 1e-5f
#define P1_BLOCKS 256
#define P1_TILES 8
#define P1_THREADS 256
#define P1P 130

// ---- device scratch --------------------------------------------------------
__device__ float gSpart[3 * P1_BLOCKS * DIN];
__device__ float gS[3 * DIN];
__device__ float gCpart[(size_t)3 * P1_BLOCKS * DIN * DIN];
__device__ float gC[3 * DIN * DIN];
__device__ __align__(16) __nv_bfloat16 gMbf[3][2][80 * 88]; // hi/lo, pitch 88
__device__ float gU[3 * DIN];
__device__ float gV[3 * DIN];
__device__ float gCc[3];

struct Params { const float *W[3], *b[3], *g[3], *be[3]; };

__device__ __forceinline__ float2 ffma2(float2 a, float2 b, float2 c) {
    float2 d;
    asm("fma.rn.f32x2 %0, %1, %2, %3;"
        : "=l"(reinterpret_cast<unsigned long long&>(d))
        : "l"(reinterpret_cast<unsigned long long&>(a)),
          "l"(reinterpret_cast<unsigned long long&>(b)),
          "l"(reinterpret_cast<unsigned long long&>(c)));
    return d;
}
__device__ __forceinline__ uint32_t smem_u32(const void* p) {
    uint32_t a;
    asm("{ .reg .u64 t; cvta.to.shared.u64 t, %1; cvt.u32.u64 %0, t; }"
        : "=r"(a) : "l"(p));
    return a;
}
__device__ __forceinline__ void ldsm4(uint32_t& a0, uint32_t& a1, uint32_t& a2,
                                      uint32_t& a3, uint32_t addr) {
    asm volatile("ldmatrix.sync.aligned.m8n8.x4.shared.b16 {%0,%1,%2,%3}, [%4];"
                 : "=r"(a0), "=r"(a1), "=r"(a2), "=r"(a3) : "r"(addr));
}
__device__ __forceinline__ void ldsm2(uint32_t& b0, uint32_t& b1, uint32_t addr) {
    asm volatile("ldmatrix.sync.aligned.m8n8.x2.shared.b16 {%0,%1}, [%2];"
                 : "=r"(b0), "=r"(b1) : "r"(addr));
}
__device__ __forceinline__ void mma16816(float* d, uint32_t a0, uint32_t a1,
                                         uint32_t a2, uint32_t a3,
                                         uint32_t b0, uint32_t b1) {
    asm volatile("mma.sync.aligned.m16n8k16.row.col.f32.bf16.bf16.f32 "
                 "{%0,%1,%2,%3}, {%4,%5,%6,%7}, {%8,%9}, {%0,%1,%2,%3};"
                 : "+f"(d[0]), "+f"(d[1]), "+f"(d[2]), "+f"(d[3])
                 : "r"(a0), "r"(a1), "r"(a2), "r"(a3), "r"(b0), "r"(b1));
}
__device__ __forceinline__ uint32_t bfpack(float a, float b) {
    __nv_bfloat162 t(__float2bfloat16(a), __float2bfloat16(b));
    return *(uint32_t*)&t;
}
__device__ __forceinline__ float2 rd2(const char* hi, const char* lo, int off) {
    __nv_bfloat162 h = *(const __nv_bfloat162*)(hi + off);
    __nv_bfloat162 l = *(const __nv_bfloat162*)(lo + off);
    return make_float2(__bfloat162float(h.x) + __bfloat162float(l.x),
                       __bfloat162float(h.y) + __bfloat162float(l.y));
}

// ---------------------------------------------------------------------------
// K1: partial X^T X (upper block-triangle) + col-sum partials (R11, unchanged)
// ---------------------------------------------------------------------------
__global__ __launch_bounds__(P1_THREADS)
void k_xtx(const float* __restrict__ X0, const float* __restrict__ X1,
           const float* __restrict__ X2)
{
    __shared__ __align__(16) float XsT[DIN * P1P];
    const int s = blockIdx.y;
    const float* X = (s == 0) ? X0 : (s == 1) ? X1 : X2;
    const int tid = threadIdx.x, tj = tid & 15, tk = tid >> 4;

    float2 acc[5][5];
#pragma unroll
    for (int a = 0; a < 5; ++a)
#pragma unroll
        for (int b = 0; b < 5; ++b) acc[a][b] = make_float2(0.f, 0.f);
    float2 cs = make_float2(0.f, 0.f);
    const float2 one2 = make_float2(1.f, 1.f);
    const long long rowbase = (long long)blockIdx.x * (P1_TILES * 128);

    for (int t = 0; t < P1_TILES; ++t) {
        const float4* src4 = (const float4*)(X + (rowbase + (long long)t * 128) * DIN);
        for (int i4 = tid; i4 < 128 * DIN / 4; i4 += P1_THREADS) {
            int r = i4 / 20, k4 = i4 - r * 20;
            float4 v = src4[i4];
            XsT[(4 * k4 + 0) * P1P + r] = v.x;
            XsT[(4 * k4 + 1) * P1P + r] = v.y;
            XsT[(4 * k4 + 2) * P1P + r] = v.z;
            XsT[(4 * k4 + 3) * P1P + r] = v.w;
        }
        __syncthreads();
#pragma unroll 4
        for (int p = 0; p < 64; ++p) {
            float2 xj[5], xk[5];
#pragma unroll
            for (int a = 0; a < 5; ++a)
                xj[a] = *(const float2*)&XsT[(tj + 16 * a) * P1P + 2 * p];
#pragma unroll
            for (int b = 0; b < 5; ++b)
                xk[b] = *(const float2*)&XsT[(tk + 16 * b) * P1P + 2 * p];
#pragma unroll
            for (int a = 0; a < 5; ++a)
#pragma unroll
                for (int b = a; b < 5; ++b)
                    acc[a][b] = ffma2(xj[a], xk[b], acc[a][b]);
        }
        if (tid < DIN) {
#pragma unroll 8
            for (int p = 0; p < 64; ++p)
                cs = ffma2(*(const float2*)&XsT[tid * P1P + 2 * p], one2, cs);
        }
        __syncthreads();
    }
    float* dst = gCpart + (size_t)(s * P1_BLOCKS + blockIdx.x) * (DIN * DIN);
#pragma unroll
    for (int a = 0; a < 5; ++a)
#pragma unroll
        for (int b = a; b < 5; ++b)
            dst[(tj + 16 * a) * DIN + (tk + 16 * b)] = acc[a][b].x + acc[a][b].y;
    if (tid < DIN) gSpart[(s * P1_BLOCKS + blockIdx.x) * DIN + tid] = cs.x + cs.y;
}

// ---------------------------------------------------------------------------
// K2: reduce partials (unchanged)
// ---------------------------------------------------------------------------
__global__ void k_reduceC()
{
    int e = blockIdx.x * blockDim.x + threadIdx.x;
    if (e < 3 * DIN * DIN) {
        int s = e / (DIN * DIN), rem = e - s * DIN * DIN;
        int j = rem / DIN, k = rem - j * DIN;
        int jt = j >> 4, kt = k >> 4;
        if (jt > kt || (jt == kt && j > k)) return;
        const float* src = gCpart + (size_t)s * P1_BLOCKS * (DIN * DIN) + rem;
        float acc = 0.f;
#pragma unroll 8
        for (int b = 0; b < P1_BLOCKS; ++b) acc += src[(size_t)b * (DIN * DIN)];
        gC[s * DIN * DIN + j * DIN + k] = acc;
        gC[s * DIN * DIN + k * DIN + j] = acc;
    } else if (e < 3 * DIN * DIN + 3 * DIN) {
        int h = e - 3 * DIN * DIN, s = h / DIN, k = h - s * DIN;
        float acc = 0.f;
#pragma unroll 8
        for (int b = 0; b < P1_BLOCKS; ++b) acc += gSpart[(s * P1_BLOCKS + b) * DIN + k];
        gS[s * DIN + k] = acc;
    }
}

// ---------------------------------------------------------------------------
// K3: fused stats + build M (split-2 bf16, [p][q] pitch 88), u, v, c.
// ---------------------------------------------------------------------------
#define WP 84
#define TPP (DOUT + 8)
#define PREP_SMEM ((2*DOUT*WP + DIN*DIN + 16*TPP + DOUT + DIN + 2*DOUT) * 4)

__global__ __launch_bounds__(256)
void k_prep(Params P, float invN)
{
    extern __shared__ __align__(16) float sp[];
    float* WsA = sp;
    float* WsB = WsA + DOUT * WP;
    float* Cs  = WsB + DOUT * WP;
    float* Tp  = Cs + DIN * DIN;
    float* alphas = Tp + 16 * TPP;
    float* xbs = alphas + DOUT;
    float* dA  = xbs + DIN;
    float* dB  = dA + DOUT;

    const int s = blockIdx.x;
    const int a_idx = (s == 2) ? 1 : 0;
    const int b_idx = (s == 0) ? 1 : 2;
    const int tid = threadIdx.x, tj = tid & 15, tk = tid >> 4;

    for (int ph = 0; ph < 2; ++ph) {
        const int t = ph ? b_idx : a_idx;
        float* Ws = ph ? WsB : WsA;
        float* dd = ph ? dB : dA;
        const float4* Wg4 = (const float4*)P.W[t];
        for (int i4 = tid; i4 < DOUT * 20; i4 += 256) {
            int j = i4 / 20, k4 = i4 - j * 20;
            *(float4*)&Ws[j * WP + 4 * k4] = Wg4[i4];
        }
        const float4* Cg4 = (const float4*)&gC[t * DIN * DIN];
        for (int i4 = tid; i4 < (DIN * DIN) / 4; i4 += 256) ((float4*)Cs)[i4] = Cg4[i4];
        if (tid < DIN) xbs[tid] = gS[t * DIN + tid] * invN;
        __syncthreads();

        float acc[10][5];
#pragma unroll
        for (int aa = 0; aa < 10; ++aa)
#pragma unroll
            for (int bb = 0; bb < 5; ++bb) acc[aa][bb] = 0.f;
        for (int m = 0; m < DIN; ++m) {
            float wv[10], cv[5];
#pragma unroll
            for (int aa = 0; aa < 10; ++aa) wv[aa] = Ws[(tj + 16 * aa) * WP + m];
#pragma unroll
            for (int bb = 0; bb < 5; ++bb) cv[bb] = Cs[m * DIN + tk + 16 * bb];
#pragma unroll
            for (int aa = 0; aa < 10; ++aa)
#pragma unroll
                for (int bb = 0; bb < 5; ++bb) acc[aa][bb] += wv[aa] * cv[bb];
        }
#pragma unroll
        for (int aa = 0; aa < 10; ++aa) {
            float ps = 0.f;
#pragma unroll
            for (int bb = 0; bb < 5; ++bb)
                ps += acc[aa][bb] * Ws[(tj + 16 * aa) * WP + tk + 16 * bb];
            Tp[tk * TPP + tj + 16 * aa] = ps;
        }
        __syncthreads();
        if (tid < DOUT) {
            float q = 0.f;
#pragma unroll
            for (int g = 0; g < 16; ++g) q += Tp[g * TPP + tid];
            float wx = 0.f;
#pragma unroll 8
            for (int m = 0; m < DIN; ++m) wx += Ws[tid * WP + m] * xbs[m];
            float bj = P.b[t][tid], mu = wx + bj;
            float var = q * invN - wx * wx;
            float alpha = P.g[t][tid] * rsqrtf(var + EPSV);
            dd[tid] = alpha * bj + (P.be[t][tid] - mu * alpha);
            alphas[tid] = alpha;
        }
        __syncthreads();
        for (int i = tid; i < DOUT * DIN; i += 256) {
            int j = i / DIN, m = i - j * DIN;
            Ws[j * WP + m] *= alphas[j];
        }
        __syncthreads();
    }

    float macc[5][5];
#pragma unroll
    for (int aa = 0; aa < 5; ++aa)
#pragma unroll
        for (int bb = 0; bb < 5; ++bb) macc[aa][bb] = 0.f;
    for (int j = 0; j < DOUT; ++j) {
        float av[5], bv[5];
#pragma unroll
        for (int aa = 0; aa < 5; ++aa) av[aa] = WsA[j * WP + tj + 16 * aa];
#pragma unroll
        for (int bb = 0; bb < 5; ++bb) bv[bb] = WsB[j * WP + tk + 16 * bb];
#pragma unroll
        for (int aa = 0; aa < 5; ++aa)
#pragma unroll
            for (int bb = 0; bb < 5; ++bb) macc[aa][bb] += av[aa] * bv[bb];
    }
    __nv_bfloat16* mh = gMbf[s][0];
    __nv_bfloat16* ml = gMbf[s][1];
#pragma unroll
    for (int aa = 0; aa < 5; ++aa)
#pragma unroll
        for (int bb = 0; bb < 5; ++bb) {
            int p = tj + 16 * aa, q = tk + 16 * bb;
            float m = macc[aa][bb];
            __nv_bfloat16 h = __float2bfloat16(m);
            mh[p * 88 + q] = h;
            ml[p * 88 + q] = __float2bfloat16(m - __bfloat162float(h));
        }
    if (tid < DIN) {
        float u = 0.f;
        for (int j = 0; j < DOUT; ++j) u += WsA[j * WP + tid] * dB[j];
        gU[s * DIN + tid] = u;
    } else if (tid < 2 * DIN) {
        int q = tid - DIN;
        float v = 0.f;
        for (int j = 0; j < DOUT; ++j) v += dA[j] * WsB[j * WP + q];
        gV[s * DIN + q] = v;
    } else if (tid == 2 * DIN) {
        float c = 0.f;
        for (int j = 0; j < DOUT; ++j) c += dA[j] * dB[j];
        gCc[s] = c;
    }
}

// ---------------------------------------------------------------------------
// K4: mma.sync main pass. 128 rows/block, 256 threads (8 warps).
// X streams as bf16 hi/lo (pitch 176B, ldmatrix conflict-free). Per pair:
// warp w owns rows 16w..16w+15; D[10][4] regs over 15 k-steps (3 split terms).
// Fragment-level epilogue: dot with x_a (+u), v.x_b, shfl-reduce -> sims.
// ---------------------------------------------------------------------------
#define XPITCH 176
#define XB(t, h) (((t) * 2 + (h)) * 22528)      // 128*176 each
#define O_M   135168                             // [2][80][88] bf16 = 28160
#define O_US  163328
#define O_VS  164288
#define O_CC  165248
#define O_SIM 165264
#define O_PSM 166800
#define KMAIN_SMEM 168448

__global__ __launch_bounds__(256, 1)
void k_main(const float* __restrict__ X0, const float* __restrict__ X1,
            const float* __restrict__ X2, float* __restrict__ out)
{
    extern __shared__ __align__(16) char smc[];
    float* us   = (float*)(smc + O_US);
    float* vs   = (float*)(smc + O_VS);
    float* ccs  = (float*)(smc + O_CC);
    float* simw = (float*)(smc + O_SIM);
    float* psm  = (float*)(smc + O_PSM);
    const uint32_t sb = smem_u32(smc);
    const int tid = threadIdx.x, wid = tid >> 5, lane = tid & 31;
    const long long base = (long long)blockIdx.x * 128;

    // phase A: convert all 3 streams to bf16 hi/lo tiles
    const float* Xp[3] = {X0, X1, X2};
    for (int t = 0; t < 3; ++t) {
        const float4* src4 = (const float4*)(Xp[t] + base * DIN);
        char* hi = smc + XB(t, 0);
        char* lo = smc + XB(t, 1);
        for (int i4 = tid; i4 < 128 * 20; i4 += 256) {
            int r = i4 / 20, q0 = 4 * (i4 - r * 20);
            float4 v = src4[i4];
            __nv_bfloat16 h0 = __float2bfloat16(v.x), h1 = __float2bfloat16(v.y);
            __nv_bfloat16 h2 = __float2bfloat16(v.z), h3 = __float2bfloat16(v.w);
            int o = r * XPITCH + q0 * 2;
            __nv_bfloat162 p01(h0, h1), p23(h2, h3);
            *(uint32_t*)(hi + o)     = *(uint32_t*)&p01;
            *(uint32_t*)(hi + o + 4) = *(uint32_t*)&p23;
            *(uint32_t*)(lo + o)     = bfpack(v.x - __bfloat162float(h0),
                                              v.y - __bfloat162float(h1));
            *(uint32_t*)(lo + o + 4) = bfpack(v.z - __bfloat162float(h2),
                                              v.w - __bfloat162float(h3));
        }
    }
    if (tid < 3 * DIN) { us[tid] = gU[tid]; vs[tid] = gV[tid]; }
    if (tid < 3)       ccs[tid] = gCc[tid];
    __syncthreads();

    const int g = lane >> 2, tq = lane & 3;
    const int aln = (lane < 16) ? lane : (lane - 16);
    const int akoff = (lane < 16) ? 0 : 16;
    const int bln = lane & 7;
    const int bkoff = (lane & 8) ? 16 : 0;

    for (int s = 0; s < 3; ++s) {
        const int aS = (s == 2) ? 1 : 0;   // x_a stream (sub, sub, left)
        const int bS = (s == 0) ? 1 : 2;   // x_b stream (left, right, right)

        // stage M hi/lo for this pair
        const float4* mg = (const float4*)gMbf[s][0];
        for (int i = tid; i < 1760; i += 256) ((float4*)(smc + O_M))[i] = mg[i];
        __syncthreads();

        float d[10][4];
#pragma unroll
        for (int n = 0; n < 10; ++n)
#pragma unroll
            for (int i = 0; i < 4; ++i) d[n][i] = 0.f;

        const uint32_t tA[3] = {sb + XB(bS, 0), sb + XB(bS, 0), sb + XB(bS, 1)};
        const uint32_t tB[3] = {sb + O_M, sb + O_M + 14080, sb + O_M};
#pragma unroll
        for (int term = 0; term < 3; ++term) {
            uint32_t abase = tA[term] + (16 * wid + aln) * XPITCH + akoff;
            uint32_t bbase = tB[term] + bln * XPITCH + bkoff;
#pragma unroll
            for (int ks = 0; ks < 5; ++ks) {
                uint32_t a0, a1, a2, a3;
                ldsm4(a0, a1, a2, a3, abase + ks * 32);
#pragma unroll
                for (int n = 0; n < 10; ++n) {
                    uint32_t b0, b1;
                    ldsm2(b0, b1, bbase + n * 8 * XPITCH + ks * 32);
                    mma16816(d[n], a0, a1, a2, a3, b0, b1);
                }
            }
        }

        // fragment epilogue: sim rows r0 = 16wid+g, r1 = r0+8
        const char* ah = smc + XB(aS, 0);
        const char* al = smc + XB(aS, 1);
        const char* bh = smc + XB(bS, 0);
        const char* bl = smc + XB(bS, 1);
        const int r0 = 16 * wid + g, r1 = r0 + 8;
        float s0 = 0.f, s1 = 0.f;
#pragma unroll
        for (int n = 0; n < 10; ++n) {
            int p0 = 8 * n + 2 * tq;
            float2 uu = *(const float2*)&us[s * DIN + p0];
            float2 vv = *(const float2*)&vs[s * DIN + p0];
            float2 xa0 = rd2(ah, al, r0 * XPITCH + p0 * 2);
            float2 xa1 = rd2(ah, al, r1 * XPITCH + p0 * 2);
            float2 xb0 = rd2(bh, bl, r0 * XPITCH + p0 * 2);
            float2 xb1 = rd2(bh, bl, r1 * XPITCH + p0 * 2);
            s0 += (d[n][0] + uu.x) * xa0.x + (d[n][1] + uu.y) * xa0.y
                + vv.x * xb0.x + vv.y * xb0.y;
            s1 += (d[n][2] + uu.x) * xa1.x + (d[n][3] + uu.y) * xa1.y
                + vv.x * xb1.x + vv.y * xb1.y;
        }
        s0 += __shfl_xor_sync(0xffffffff, s0, 1);
        s0 += __shfl_xor_sync(0xffffffff, s0, 2);
        s1 += __shfl_xor_sync(0xffffffff, s1, 1);
        s1 += __shfl_xor_sync(0xffffffff, s1, 2);
        if (tq == 0) {
            simw[s * 128 + r0] = s0;
            simw[s * 128 + r1] = s1;
        }
        __syncthreads();   // sims written; M smem free for next pair
    }

    // softmax per row
    if (tid < 128) {
        float s0 = simw[tid] + ccs[0];
        float s1 = simw[128 + tid] + ccs[1];
        float s2 = simw[256 + tid] + ccs[2];
        float m = fmaxf(s0, fmaxf(s1, s2));
        float e0 = __expf(s0 - m), e1 = __expf(s1 - m), e2 = __expf(s2 - m);
        float inv = 1.f / (e0 + e1 + e2);
        psm[tid] = e0 * inv;
        psm[128 + tid] = e1 * inv;
        psm[256 + tid] = e2 * inv;
    }
    __syncthreads();

    // blend (coalesced): out = p0*left + p1*right + p2*sub
    const float4* s4 = (const float4*)(X0 + base * DIN);
    const float4* l4 = (const float4*)(X1 + base * DIN);
    const float4* r4 = (const float4*)(X2 + base * DIN);
    float4* d4 = (float4*)(out + base * DIN);
    for (int i4 = tid; i4 < 128 * 20; i4 += 256) {
        int r = i4 / 20;
        float p0 = psm[r], p1 = psm[128 + r], p2 = psm[256 + r];
        float4 a = s4[i4], b = l4[i4], c = r4[i4], o;
        o.x = p0 * b.x + p1 * c.x + p2 * a.x;
        o.y = p0 * b.y + p1 * c.y + p2 * a.y;
        o.z = p0 * b.z + p1 * c.z + p2 * a.z;
        o.w = p0 * b.w + p1 * c.w + p2 * a.w;
        d4[i4] = o;
    }
}

// ---------------------------------------------------------------------------
extern "C" void kernel_launch(void* const* d_in, const int* in_sizes, int n_in,
                              void* d_out, int out_size)
{
    const float* sub   = (const float*)d_in[0];
    const float* left  = (const float*)d_in[1];
    const float* right = (const float*)d_in[2];
    Params P;
    for (int s = 0; s < 3; ++s) {
        P.W[s]  = (const float*)d_in[3 + 4 * s + 0];
        P.b[s]  = (const float*)d_in[3 + 4 * s + 1];
        P.g[s]  = (const float*)d_in[3 + 4 * s + 2];
        P.be[s] = (const float*)d_in[3 + 4 * s + 3];
    }
    cudaFuncSetAttribute(k_prep, cudaFuncAttributeMaxDynamicSharedMemorySize, PREP_SMEM);
    cudaFuncSetAttribute(k_main, cudaFuncAttributeMaxDynamicSharedMemorySize, KMAIN_SMEM);

    k_xtx<<<dim3(P1_BLOCKS, 3), P1_THREADS>>>(sub, left, right);
    k_reduceC<<<(3 * DIN * DIN + 3 * DIN + 255) / 256, 256>>>();
    k_prep<<<3, 256, PREP_SMEM>>>(P, 1.0f / (float)NROWS);
    k_main<<<NROWS / 128, 256, KMAIN_SMEM>>>(sub, left, right, (float*)d_out);
}